// round 1
// baseline (speedup 1.0000x reference)
#include <cuda_runtime.h>
#include <math.h>

// Problem dims
#define BB 128
#define SS 64
#define UU 512
#define VV 32000
#define XC 1024   // 2U
#define G3 1536   // 3U

// Output layout: [logits (128*32000)] [state (128*512)] [alpha (128*64)]
#define STATE_OFF (BB*VV)
#define ALPHA_OFF (BB*VV + BB*UU)

// Scratch (device globals: allocation-free)
__device__ float g_E[BB*SS*UU];   // tanh(attn@W0+b0+b1), 16.8 MB
__device__ float g_xc[BB*XC];     // [emb gather | context]
__device__ float g_U[BB*G3];      // xc@gru_k + gru_b[0]
__device__ float g_y[BB*UU];      // relu(state@dW+db)

// ---------------------------------------------------------------------------
// SGEMM 128x128 tile, BK=8, 256 threads, 8x8 per thread.
// C = epi(A[M,K] @ B[K,N] + bias1 (+bias2)), all row-major.
// EPI: 0 = bias, 1 = bias1+bias2 then tanh, 2 = bias then relu
// Requires M%128==0 handled by grid covering exactly, N%128==0, K%8==0.
// ---------------------------------------------------------------------------
template<int EPI>
__global__ __launch_bounds__(256) void sgemm128(
    const float* __restrict__ A, const float* __restrict__ Bm,
    float* __restrict__ C,
    const float* __restrict__ bias1, const float* __restrict__ bias2,
    int M, int N, int K)
{
    __shared__ float As[128][8];   // [row][k] : conflict-free stores, broadcast reads
    __shared__ float Bs[8][128];

    const int tid = threadIdx.x;
    const int bm  = blockIdx.y * 128;
    const int bn  = blockIdx.x * 128;
    const int tx  = tid & 15;      // 0..15 -> col group (8 cols)
    const int ty  = tid >> 4;      // 0..15 -> row group (8 rows)

    // A tile loads: 128 rows x 8 k = 1024 floats = 256 float4
    const int a_row = tid >> 1;          // 0..127
    const int a_col = (tid & 1) * 4;     // 0 or 4
    // B tile loads: 8 k x 128 cols = 256 float4
    const int b_row = tid >> 5;          // 0..7
    const int b_col = (tid & 31) * 4;    // 0..124

    const float* Aptr = A  + (size_t)(bm + a_row) * K + a_col;
    const float* Bptr = Bm + (size_t)b_row * N + bn + b_col;

    float acc[8][8];
#pragma unroll
    for (int i = 0; i < 8; i++)
#pragma unroll
        for (int j = 0; j < 8; j++) acc[i][j] = 0.0f;

    for (int k0 = 0; k0 < K; k0 += 8) {
        float4 av = *(const float4*)(Aptr + k0);
        *(float4*)&As[a_row][a_col] = av;
        *(float4*)&Bs[b_row][b_col] = *(const float4*)(Bptr + (size_t)k0 * N);
        __syncthreads();

#pragma unroll
        for (int kk = 0; kk < 8; kk++) {
            float ar[8], br[8];
#pragma unroll
            for (int i = 0; i < 8; i++) ar[i] = As[ty*8 + i][kk];
            *(float4*)(br)     = *(float4*)&Bs[kk][tx*8];
            *(float4*)(br + 4) = *(float4*)&Bs[kk][tx*8 + 4];
#pragma unroll
            for (int i = 0; i < 8; i++)
#pragma unroll
                for (int j = 0; j < 8; j++) acc[i][j] += ar[i] * br[j];
        }
        __syncthreads();
    }

    // Epilogue: vectorized float4 stores
#pragma unroll
    for (int i = 0; i < 8; i++) {
        const int row = bm + ty*8 + i;
        float v[8];
#pragma unroll
        for (int j = 0; j < 8; j++) {
            const int col = bn + tx*8 + j;
            float x = acc[i][j];
            if (bias1) x += bias1[col];
            if (EPI == 1) { if (bias2) x += bias2[col]; x = tanhf(x); }
            if (EPI == 2) { x = fmaxf(x, 0.0f); }
            v[j] = x;
        }
        float* cp = C + (size_t)row * N + bn + tx*8;
        *(float4*)(cp)     = make_float4(v[0], v[1], v[2], v[3]);
        *(float4*)(cp + 4) = make_float4(v[4], v[5], v[6], v[7]);
    }
}

// ---------------------------------------------------------------------------
// SGEMM 64x64 tile, BK=16, 256 threads, 4x4 per thread (for small-M GEMMs).
// ---------------------------------------------------------------------------
template<int EPI>
__global__ __launch_bounds__(256) void sgemm64(
    const float* __restrict__ A, const float* __restrict__ Bm,
    float* __restrict__ C,
    const float* __restrict__ bias1,
    int M, int N, int K)
{
    __shared__ float As[64][16];
    __shared__ float Bs[16][64];

    const int tid = threadIdx.x;
    const int bm  = blockIdx.y * 64;
    const int bn  = blockIdx.x * 64;
    const int tx  = tid & 15;
    const int ty  = tid >> 4;

    const int a_row = tid >> 2;          // 0..63
    const int a_col = (tid & 3) * 4;     // 0,4,8,12
    const int b_row = tid >> 4;          // 0..15
    const int b_col = (tid & 15) * 4;    // 0..60

    const float* Aptr = A  + (size_t)(bm + a_row) * K + a_col;
    const float* Bptr = Bm + (size_t)b_row * N + bn + b_col;

    float acc[4][4];
#pragma unroll
    for (int i = 0; i < 4; i++)
#pragma unroll
        for (int j = 0; j < 4; j++) acc[i][j] = 0.0f;

    for (int k0 = 0; k0 < K; k0 += 16) {
        *(float4*)&As[a_row][a_col] = *(const float4*)(Aptr + k0);
        *(float4*)&Bs[b_row][b_col] = *(const float4*)(Bptr + (size_t)k0 * N);
        __syncthreads();

#pragma unroll
        for (int kk = 0; kk < 16; kk++) {
            float ar[4], br[4];
#pragma unroll
            for (int i = 0; i < 4; i++) ar[i] = As[ty*4 + i][kk];
            *(float4*)(br) = *(float4*)&Bs[kk][tx*4];
#pragma unroll
            for (int i = 0; i < 4; i++)
#pragma unroll
                for (int j = 0; j < 4; j++) acc[i][j] += ar[i] * br[j];
        }
        __syncthreads();
    }

#pragma unroll
    for (int i = 0; i < 4; i++) {
        const int row = bm + ty*4 + i;
        float v[4];
#pragma unroll
        for (int j = 0; j < 4; j++) {
            const int col = bn + tx*4 + j;
            float x = acc[i][j];
            if (bias1) x += bias1[col];
            if (EPI == 2) x = fmaxf(x, 0.0f);
            v[j] = x;
        }
        float* cp = C + (size_t)row * N + bn + tx*4;
        *(float4*)cp = make_float4(v[0], v[1], v[2], v[3]);
    }
}

// ---------------------------------------------------------------------------
// Attention reduction: score = E@vW + vb, softmax over S, context = sum alpha*attn.
// Also builds xc = [emb[inputs[b]], context]. One block per batch row.
// ---------------------------------------------------------------------------
__global__ __launch_bounds__(256) void attn_reduce(
    const float* __restrict__ attn, const float* __restrict__ vW,
    const float* __restrict__ vb,  const int* __restrict__ inputs,
    const float* __restrict__ emb, float* __restrict__ out_alpha)
{
    __shared__ float sc[SS];
    const int b = blockIdx.x;
    const int tid = threadIdx.x;
    const int warp = tid >> 5;
    const int lane = tid & 31;

    // scores: warp w handles s = w*8 .. w*8+7
#pragma unroll
    for (int q = 0; q < 8; q++) {
        const int s = warp * 8 + q;
        const float* e = g_E + (size_t)(b * SS + s) * UU;
        float acc = 0.0f;
        for (int u = lane; u < UU; u += 32) acc += e[u] * vW[u];
#pragma unroll
        for (int o = 16; o; o >>= 1) acc += __shfl_xor_sync(0xffffffffu, acc, o);
        if (lane == 0) sc[s] = acc + vb[0];
    }
    __syncthreads();

    // softmax over 64 scores (warp 0, 2 per lane)
    if (warp == 0) {
        float v0 = sc[lane], v1 = sc[lane + 32];
        float m = fmaxf(v0, v1);
#pragma unroll
        for (int o = 16; o; o >>= 1) m = fmaxf(m, __shfl_xor_sync(0xffffffffu, m, o));
        float e0 = expf(v0 - m), e1 = expf(v1 - m);
        float ssum = e0 + e1;
#pragma unroll
        for (int o = 16; o; o >>= 1) ssum += __shfl_xor_sync(0xffffffffu, ssum, o);
        const float inv = 1.0f / ssum;
        sc[lane]      = e0 * inv;
        sc[lane + 32] = e1 * inv;
        out_alpha[b * SS + lane]      = e0 * inv;
        out_alpha[b * SS + lane + 32] = e1 * inv;
    }
    __syncthreads();

    // context + emb gather -> xc
    const int erow = inputs[b];
    for (int u = tid; u < UU; u += 256) {
        float c = 0.0f;
        const float* ap = attn + (size_t)(b * SS) * UU + u;
#pragma unroll 8
        for (int s = 0; s < SS; s++) c += sc[s] * ap[(size_t)s * UU];
        g_xc[b * XC + UU + u] = c;
        g_xc[b * XC + u] = emb[(size_t)erow * UU + u];
    }
}

// ---------------------------------------------------------------------------
// GRU gates (h = 0): z=sig(xz+b1z), r=sig(xr+b1r), hh=tanh(xh + r*b1h),
// state = (1-z)*hh.  g_U already contains xc@gru_k + gru_b[0].
// ---------------------------------------------------------------------------
__global__ __launch_bounds__(256) void gru_gates(
    const float* __restrict__ gru_b, float* __restrict__ out_state)
{
    const int i = blockIdx.x * blockDim.x + threadIdx.x;  // 0..65535
    const int b = i >> 9;
    const int n = i & 511;
    const float* gb1 = gru_b + G3;   // gru_b[1]
    const float* u = g_U + (size_t)b * G3;
    const float xz = u[n]        + gb1[n];
    const float xr = u[512 + n]  + gb1[512 + n];
    const float xh = u[1024 + n];
    const float z = 1.0f / (1.0f + expf(-xz));
    const float r = 1.0f / (1.0f + expf(-xr));
    const float hh = tanhf(xh + r * gb1[1024 + n]);
    out_state[i] = (1.0f - z) * hh;
}

// ---------------------------------------------------------------------------
extern "C" void kernel_launch(void* const* d_in, const int* in_sizes, int n_in,
                              void* d_out, int out_size)
{
    (void)in_sizes; (void)n_in; (void)out_size;

    const int*   inputs = (const int*)  d_in[0];
    const float* attn   = (const float*)d_in[1];
    const float* W0     = (const float*)d_in[2];
    const float* b0     = (const float*)d_in[3];
    // d_in[4] = W1 (unused: hidden0 == 0)
    const float* b1     = (const float*)d_in[5];
    const float* vW     = (const float*)d_in[6];
    const float* vb     = (const float*)d_in[7];
    const float* emb    = (const float*)d_in[8];
    const float* gru_k  = (const float*)d_in[9];
    // d_in[10] = gru_rk (unused: h == 0)
    const float* gru_b  = (const float*)d_in[11];
    const float* dW     = (const float*)d_in[12];
    const float* db     = (const float*)d_in[13];
    const float* oW     = (const float*)d_in[14];
    const float* ob     = (const float*)d_in[15];
    float* out = (float*)d_out;

    float *pE, *pXC, *pU, *pY;
    cudaGetSymbolAddress((void**)&pE,  g_E);
    cudaGetSymbolAddress((void**)&pXC, g_xc);
    cudaGetSymbolAddress((void**)&pU,  g_U);
    cudaGetSymbolAddress((void**)&pY,  g_y);

    // 1) E = tanh(attn2d @ W0 + b0 + b1)   [8192 x 512 x 512]
    sgemm128<1><<<dim3(UU/128, (BB*SS)/128), 256>>>(attn, W0, pE, b0, b1,
                                                    BB*SS, UU, UU);
    // 2) score -> softmax -> alpha(out) -> context; build xc
    attn_reduce<<<BB, 256>>>(attn, vW, vb, inputs, emb, out + ALPHA_OFF);

    // 3) U = xc @ gru_k + gru_b[0]          [128 x 1536 x 1024]
    sgemm64<0><<<dim3(G3/64, BB/64), 256>>>(pXC, gru_k, pU, gru_b,
                                            BB, G3, XC);
    // 4) gates -> state (written straight into d_out)
    gru_gates<<<(BB*UU)/256, 256>>>(gru_b, out + STATE_OFF);

    // 5) y = relu(state @ dW + db)          [128 x 512 x 512]
    sgemm64<2><<<dim3(UU/64, BB/64), 256>>>(out + STATE_OFF, dW, pY, db,
                                            BB, UU, UU);
    // 6) logits = y @ oW + ob               [128 x 32000 x 512] -> d_out
    sgemm128<0><<<dim3(VV/128, BB/128), 256>>>(pY, oW, out, ob, nullptr,
                                               BB, VV, UU);
}

// round 2
// speedup vs baseline: 2.6180x; 2.6180x over previous
#include <cuda_runtime.h>
#include <math.h>
#include <stdint.h>

// Problem dims
#define BB 128
#define SS 64
#define UU 512
#define VV 32000
#define XC 1024   // 2U
#define G3 1536   // 3U

// Output layout: [logits (128*32000)] [state (128*512)] [alpha (128*64)]
#define STATE_OFF (BB*VV)
#define ALPHA_OFF (BB*VV + BB*UU)

// Scratch (device globals: allocation-free)
__device__ float g_E[BB*SS*UU];   // tanh(attn@W0+b0+b1)
__device__ float g_xc[BB*XC];     // [emb gather | context]
__device__ float g_U[BB*G3];      // xc@gru_k + gru_b[0]
__device__ float g_y[BB*UU];      // relu(state@dW+db)

// ---------------------------------------------------------------------------
// tf32 helpers
// ---------------------------------------------------------------------------
__device__ __forceinline__ uint32_t f2tf32(float x) {
    uint32_t r;
    asm("cvt.rna.tf32.f32 %0, %1;" : "=r"(r) : "f"(x));
    return r;
}

__device__ __forceinline__ void mma8(float* c, const uint32_t* a, const uint32_t* b) {
    asm volatile(
        "mma.sync.aligned.m16n8k8.row.col.f32.tf32.tf32.f32 "
        "{%0,%1,%2,%3},{%4,%5,%6,%7},{%8,%9},{%0,%1,%2,%3};"
        : "+f"(c[0]), "+f"(c[1]), "+f"(c[2]), "+f"(c[3])
        : "r"(a[0]), "r"(a[1]), "r"(a[2]), "r"(a[3]),
          "r"(b[0]), "r"(b[1]));
}

// ---------------------------------------------------------------------------
// TF32 MMA GEMM, 128x128 block tile, BK=32, 256 threads (8 warps, 2x4),
// warp tile 64x32 (4 m-frags x 4 n-frags of m16n8k8).
// C = epi(A[M,K] @ B[K,N] + bias1 (+bias2)), row-major.
// EPI: 0 = bias, 1 = bias1+bias2 then tanh, 2 = bias then relu
// Requires M%128==0, N%128==0, K%32==0.
// Smem pads chosen for conflict-free fragment reads:
//   As stride 36: bank = (4*row + k) % 32  -> 32 distinct
//   Bs stride 136: bank = (8*k + n) % 32   -> 32 distinct
// ---------------------------------------------------------------------------
template<int EPI>
__global__ __launch_bounds__(256) void mma128(
    const float* __restrict__ A, const float* __restrict__ Bm,
    float* __restrict__ C,
    const float* __restrict__ bias1, const float* __restrict__ bias2,
    int M, int N, int K)
{
    __shared__ uint32_t As[128][36];
    __shared__ uint32_t Bs[32][136];

    const int tid  = threadIdx.x;
    const int warp = tid >> 5;
    const int lane = tid & 31;
    const int wm   = (warp >> 2) * 64;   // warp row offset in block
    const int wn   = (warp & 3) * 32;    // warp col offset in block
    const int bm   = blockIdx.y * 128;
    const int bn   = blockIdx.x * 128;
    const int lr   = lane >> 2;          // 0..7
    const int lc   = lane & 3;           // 0..3

    float acc[4][4][4];
#pragma unroll
    for (int mi = 0; mi < 4; mi++)
#pragma unroll
        for (int ni = 0; ni < 4; ni++)
#pragma unroll
            for (int q = 0; q < 4; q++) acc[mi][ni][q] = 0.0f;

    for (int k0 = 0; k0 < K; k0 += 32) {
        // Load A tile 128x32 (1024 float4, 4 per thread)
#pragma unroll
        for (int it = 0; it < 4; it++) {
            const int idx = it * 256 + tid;
            const int r  = idx >> 3;
            const int kq = (idx & 7) * 4;
            float4 v = *(const float4*)(A + (size_t)(bm + r) * K + k0 + kq);
            As[r][kq + 0] = f2tf32(v.x);
            As[r][kq + 1] = f2tf32(v.y);
            As[r][kq + 2] = f2tf32(v.z);
            As[r][kq + 3] = f2tf32(v.w);
        }
        // Load B tile 32x128
#pragma unroll
        for (int it = 0; it < 4; it++) {
            const int idx = it * 256 + tid;
            const int r  = idx >> 5;
            const int cq = (idx & 31) * 4;
            float4 v = *(const float4*)(Bm + (size_t)(k0 + r) * N + bn + cq);
            Bs[r][cq + 0] = f2tf32(v.x);
            Bs[r][cq + 1] = f2tf32(v.y);
            Bs[r][cq + 2] = f2tf32(v.z);
            Bs[r][cq + 3] = f2tf32(v.w);
        }
        __syncthreads();

#pragma unroll
        for (int ks = 0; ks < 4; ks++) {
            const int kb = ks * 8;
            uint32_t af[4][4];
#pragma unroll
            for (int mi = 0; mi < 4; mi++) {
                const int r = wm + mi * 16 + lr;
                const int c = kb + lc;
                af[mi][0] = As[r][c];
                af[mi][1] = As[r + 8][c];
                af[mi][2] = As[r][c + 4];
                af[mi][3] = As[r + 8][c + 4];
            }
            uint32_t bf[4][2];
#pragma unroll
            for (int ni = 0; ni < 4; ni++) {
                const int cc = wn + ni * 8 + lr;
                const int rr = kb + lc;
                bf[ni][0] = Bs[rr][cc];
                bf[ni][1] = Bs[rr + 4][cc];
            }
#pragma unroll
            for (int mi = 0; mi < 4; mi++)
#pragma unroll
                for (int ni = 0; ni < 4; ni++)
                    mma8(acc[mi][ni], af[mi], bf[ni]);
        }
        __syncthreads();
    }

    // Epilogue: each (mi,ni) frag stores 2 rows x 1 float2
#pragma unroll
    for (int mi = 0; mi < 4; mi++) {
#pragma unroll
        for (int ni = 0; ni < 4; ni++) {
            const int r0 = bm + wm + mi * 16 + lr;
            const int c0 = bn + wn + ni * 8 + lc * 2;
            float b1v0 = bias1 ? bias1[c0]     : 0.0f;
            float b1v1 = bias1 ? bias1[c0 + 1] : 0.0f;
#pragma unroll
            for (int h = 0; h < 2; h++) {
                float x0 = acc[mi][ni][h * 2 + 0] + b1v0;
                float x1 = acc[mi][ni][h * 2 + 1] + b1v1;
                if (EPI == 1) {
                    x0 = tanhf(x0 + bias2[c0]);
                    x1 = tanhf(x1 + bias2[c0 + 1]);
                }
                if (EPI == 2) { x0 = fmaxf(x0, 0.0f); x1 = fmaxf(x1, 0.0f); }
                *(float2*)(C + (size_t)(r0 + h * 8) * N + c0) = make_float2(x0, x1);
            }
        }
    }
}

// ---------------------------------------------------------------------------
// TF32 MMA GEMM, 64x64 block tile, BK=32, 256 threads (8 warps, 2x4),
// warp tile 32x16 (2 m-frags x 2 n-frags). For M=128 GEMMs (more blocks).
// ---------------------------------------------------------------------------
template<int EPI>
__global__ __launch_bounds__(256) void mma64(
    const float* __restrict__ A, const float* __restrict__ Bm,
    float* __restrict__ C,
    const float* __restrict__ bias1,
    int M, int N, int K)
{
    __shared__ uint32_t As[64][36];
    __shared__ uint32_t Bs[32][72];

    const int tid  = threadIdx.x;
    const int warp = tid >> 5;
    const int lane = tid & 31;
    const int wm   = (warp >> 2) * 32;
    const int wn   = (warp & 3) * 16;
    const int bm   = blockIdx.y * 64;
    const int bn   = blockIdx.x * 64;
    const int lr   = lane >> 2;
    const int lc   = lane & 3;

    float acc[2][2][4];
#pragma unroll
    for (int mi = 0; mi < 2; mi++)
#pragma unroll
        for (int ni = 0; ni < 2; ni++)
#pragma unroll
            for (int q = 0; q < 4; q++) acc[mi][ni][q] = 0.0f;

    for (int k0 = 0; k0 < K; k0 += 32) {
        // A tile 64x32 = 512 float4, 2 per thread
#pragma unroll
        for (int it = 0; it < 2; it++) {
            const int idx = it * 256 + tid;
            const int r  = idx >> 3;
            const int kq = (idx & 7) * 4;
            float4 v = *(const float4*)(A + (size_t)(bm + r) * K + k0 + kq);
            As[r][kq + 0] = f2tf32(v.x);
            As[r][kq + 1] = f2tf32(v.y);
            As[r][kq + 2] = f2tf32(v.z);
            As[r][kq + 3] = f2tf32(v.w);
        }
        // B tile 32x64 = 512 float4
#pragma unroll
        for (int it = 0; it < 2; it++) {
            const int idx = it * 256 + tid;
            const int r  = idx >> 4;
            const int cq = (idx & 15) * 4;
            float4 v = *(const float4*)(Bm + (size_t)(k0 + r) * N + bn + cq);
            Bs[r][cq + 0] = f2tf32(v.x);
            Bs[r][cq + 1] = f2tf32(v.y);
            Bs[r][cq + 2] = f2tf32(v.z);
            Bs[r][cq + 3] = f2tf32(v.w);
        }
        __syncthreads();

#pragma unroll
        for (int ks = 0; ks < 4; ks++) {
            const int kb = ks * 8;
            uint32_t af[2][4];
#pragma unroll
            for (int mi = 0; mi < 2; mi++) {
                const int r = wm + mi * 16 + lr;
                const int c = kb + lc;
                af[mi][0] = As[r][c];
                af[mi][1] = As[r + 8][c];
                af[mi][2] = As[r][c + 4];
                af[mi][3] = As[r + 8][c + 4];
            }
            uint32_t bf[2][2];
#pragma unroll
            for (int ni = 0; ni < 2; ni++) {
                const int cc = wn + ni * 8 + lr;
                const int rr = kb + lc;
                bf[ni][0] = Bs[rr][cc];
                bf[ni][1] = Bs[rr + 4][cc];
            }
#pragma unroll
            for (int mi = 0; mi < 2; mi++)
#pragma unroll
                for (int ni = 0; ni < 2; ni++)
                    mma8(acc[mi][ni], af[mi], bf[ni]);
        }
        __syncthreads();
    }

#pragma unroll
    for (int mi = 0; mi < 2; mi++) {
#pragma unroll
        for (int ni = 0; ni < 2; ni++) {
            const int r0 = bm + wm + mi * 16 + lr;
            const int c0 = bn + wn + ni * 8 + lc * 2;
            float b1v0 = bias1 ? bias1[c0]     : 0.0f;
            float b1v1 = bias1 ? bias1[c0 + 1] : 0.0f;
#pragma unroll
            for (int h = 0; h < 2; h++) {
                float x0 = acc[mi][ni][h * 2 + 0] + b1v0;
                float x1 = acc[mi][ni][h * 2 + 1] + b1v1;
                if (EPI == 2) { x0 = fmaxf(x0, 0.0f); x1 = fmaxf(x1, 0.0f); }
                *(float2*)(C + (size_t)(r0 + h * 8) * N + c0) = make_float2(x0, x1);
            }
        }
    }
}

// ---------------------------------------------------------------------------
// Attention reduction: score = E@vW + vb, softmax over S, context = sum alpha*attn.
// Also builds xc = [emb[inputs[b]], context]. One block per batch row.
// ---------------------------------------------------------------------------
__global__ __launch_bounds__(256) void attn_reduce(
    const float* __restrict__ attn, const float* __restrict__ vW,
    const float* __restrict__ vb,  const int* __restrict__ inputs,
    const float* __restrict__ emb, float* __restrict__ out_alpha)
{
    __shared__ float sc[SS];
    const int b = blockIdx.x;
    const int tid = threadIdx.x;
    const int warp = tid >> 5;
    const int lane = tid & 31;

#pragma unroll
    for (int q = 0; q < 8; q++) {
        const int s = warp * 8 + q;
        const float* e = g_E + (size_t)(b * SS + s) * UU;
        float acc = 0.0f;
        for (int u = lane; u < UU; u += 32) acc += e[u] * vW[u];
#pragma unroll
        for (int o = 16; o; o >>= 1) acc += __shfl_xor_sync(0xffffffffu, acc, o);
        if (lane == 0) sc[s] = acc + vb[0];
    }
    __syncthreads();

    if (warp == 0) {
        float v0 = sc[lane], v1 = sc[lane + 32];
        float m = fmaxf(v0, v1);
#pragma unroll
        for (int o = 16; o; o >>= 1) m = fmaxf(m, __shfl_xor_sync(0xffffffffu, m, o));
        float e0 = expf(v0 - m), e1 = expf(v1 - m);
        float ssum = e0 + e1;
#pragma unroll
        for (int o = 16; o; o >>= 1) ssum += __shfl_xor_sync(0xffffffffu, ssum, o);
        const float inv = 1.0f / ssum;
        sc[lane]      = e0 * inv;
        sc[lane + 32] = e1 * inv;
        out_alpha[b * SS + lane]      = e0 * inv;
        out_alpha[b * SS + lane + 32] = e1 * inv;
    }
    __syncthreads();

    const int erow = inputs[b];
    for (int u = tid; u < UU; u += 256) {
        float c = 0.0f;
        const float* ap = attn + (size_t)(b * SS) * UU + u;
#pragma unroll 8
        for (int s = 0; s < SS; s++) c += sc[s] * ap[(size_t)s * UU];
        g_xc[b * XC + UU + u] = c;
        g_xc[b * XC + u] = emb[(size_t)erow * UU + u];
    }
}

// ---------------------------------------------------------------------------
// GRU gates (h = 0): state = (1-z)*tanh(xh + r*b1h), z/r from sigmoid.
// ---------------------------------------------------------------------------
__global__ __launch_bounds__(256) void gru_gates(
    const float* __restrict__ gru_b, float* __restrict__ out_state)
{
    const int i = blockIdx.x * blockDim.x + threadIdx.x;
    const int b = i >> 9;
    const int n = i & 511;
    const float* gb1 = gru_b + G3;
    const float* u = g_U + (size_t)b * G3;
    const float xz = u[n]       + gb1[n];
    const float xr = u[512 + n] + gb1[512 + n];
    const float xh = u[1024 + n];
    const float z = 1.0f / (1.0f + expf(-xz));
    const float r = 1.0f / (1.0f + expf(-xr));
    const float hh = tanhf(xh + r * gb1[1024 + n]);
    out_state[i] = (1.0f - z) * hh;
}

// ---------------------------------------------------------------------------
extern "C" void kernel_launch(void* const* d_in, const int* in_sizes, int n_in,
                              void* d_out, int out_size)
{
    (void)in_sizes; (void)n_in; (void)out_size;

    const int*   inputs = (const int*)  d_in[0];
    const float* attn   = (const float*)d_in[1];
    const float* W0     = (const float*)d_in[2];
    const float* b0     = (const float*)d_in[3];
    // d_in[4] = W1 (unused: hidden0 == 0)
    const float* b1     = (const float*)d_in[5];
    const float* vW     = (const float*)d_in[6];
    const float* vb     = (const float*)d_in[7];
    const float* emb    = (const float*)d_in[8];
    const float* gru_k  = (const float*)d_in[9];
    // d_in[10] = gru_rk (unused: h == 0)
    const float* gru_b  = (const float*)d_in[11];
    const float* dW     = (const float*)d_in[12];
    const float* db     = (const float*)d_in[13];
    const float* oW     = (const float*)d_in[14];
    const float* ob     = (const float*)d_in[15];
    float* out = (float*)d_out;

    float *pE, *pXC, *pU, *pY;
    cudaGetSymbolAddress((void**)&pE,  g_E);
    cudaGetSymbolAddress((void**)&pXC, g_xc);
    cudaGetSymbolAddress((void**)&pU,  g_U);
    cudaGetSymbolAddress((void**)&pY,  g_y);

    // 1) E = tanh(attn2d @ W0 + b0 + b1)   [8192 x 512 x 512] tf32 tensor
    mma128<1><<<dim3(UU/128, (BB*SS)/128), 256>>>(attn, W0, pE, b0, b1,
                                                  BB*SS, UU, UU);
    // 2) score -> softmax -> alpha(out) -> context; build xc
    attn_reduce<<<BB, 256>>>(attn, vW, vb, inputs, emb, out + ALPHA_OFF);

    // 3) U = xc @ gru_k + gru_b[0]          [128 x 1536 x 1024] tf32 tensor
    mma64<0><<<dim3(G3/64, BB/64), 256>>>(pXC, gru_k, pU, gru_b,
                                          BB, G3, XC);
    // 4) gates -> state (written straight into d_out)
    gru_gates<<<(BB*UU)/256, 256>>>(gru_b, out + STATE_OFF);

    // 5) y = relu(state @ dW + db)          [128 x 512 x 512] tf32 tensor
    mma64<2><<<dim3(UU/64, BB/64), 256>>>(out + STATE_OFF, dW, pY, db,
                                          BB, UU, UU);
    // 6) logits = y @ oW + ob               [128 x 32000 x 512] tf32 tensor
    mma128<0><<<dim3(VV/128, BB/128), 256>>>(pY, oW, out, ob, nullptr,
                                             BB, VV, UU);
}